// round 16
// baseline (speedup 1.0000x reference)
#include <cuda_runtime.h>
#include <cuda_fp16.h>
#include <math.h>
#include <stdint.h>

// Problem constants
#define BATCH 2
#define SEQ   2048
#define HEADS 16
#define DK    64
#define DM    1024
#define MROWS (BATCH * SEQ)   // 4096

// Scratch (device globals — no allocation allowed).
// All half tensors keep the contraction dim PERMUTED within 16-groups:
// stored order [0,1,8,9, 2,3,10,11, 4,5,12,13, 6,7,14,15], so an fp16 mma
// fragment's k-pair regs {(2t,2t+1),(2t+8,2t+9)} are 4 contiguous halves.
__device__ __half g_X[MROWS * DM];                  // k permuted
__device__ __half g_Wall[4 * DM * DM];              // k permuted
__device__ __half g_Q[BATCH * HEADS * SEQ * DK];    // dk permuted, pre-scaled
__device__ __half g_K[BATCH * HEADS * SEQ * DK];    // dk permuted
__device__ __half g_V[BATCH * HEADS * DK * SEQ];    // TRANSPOSED [B,H,dk,T]
__device__ __half g_ctx[MROWS * DM];                // feature permuted

__device__ __forceinline__ uint32_t f2h2(float a, float b) {
    __half2 h = __floats2half2_rn(a, b);
    return *reinterpret_cast<uint32_t*>(&h);
}
__device__ __forceinline__ float ex2f_(float x) {
    float y;
    asm("ex2.approx.ftz.f32 %0, %1;" : "=f"(y) : "f"(x));
    return y;
}

__device__ __forceinline__ void mma_f16(float c[4],
    uint32_t a0, uint32_t a1, uint32_t a2, uint32_t a3,
    uint32_t b0, uint32_t b1)
{
    asm volatile(
        "mma.sync.aligned.m16n8k16.row.col.f32.f16.f16.f32 "
        "{%0,%1,%2,%3}, {%4,%5,%6,%7}, {%8,%9}, {%0,%1,%2,%3};\n"
        : "+f"(c[0]), "+f"(c[1]), "+f"(c[2]), "+f"(c[3])
        : "r"(a0), "r"(a1), "r"(a2), "r"(a3), "r"(b0), "r"(b1));
}

__device__ __forceinline__ void cp16h(__half* smem_dst, const __half* gsrc) {
    uint32_t s = (uint32_t)__cvta_generic_to_shared(smem_dst);
    asm volatile("cp.async.cg.shared.global [%0], [%1], 16;\n" :: "r"(s), "l"(gsrc));
}
__device__ __forceinline__ void cp_commit() {
    asm volatile("cp.async.commit_group;\n");
}
template <int N>
__device__ __forceinline__ void cp_wait() {
    asm volatile("cp.async.wait_group %0;\n" :: "n"(N));
}

// ---------------------------------------------------------------------------
// Prepass: fp32 -> fp16 with 16-group k-permutation. Load-balanced flat index
// space; TWO 16-float groups per thread (8x LDG.128 -> 4x STG.128, MLP=8).
// ---------------------------------------------------------------------------
#define NXG (MROWS * DM / 16)   // 262144 x-groups
#define NWG (DM * DM / 16)      // 65536 groups per weight matrix
#define NPREP (NXG + 4 * NWG)   // 524288 total 16-groups
#define NPREP2 (NPREP / 2)      // 262144 threads (2 groups each)

__device__ __forceinline__ void perm32(const float4* __restrict__ src,
                                       uint4* __restrict__ dst)   // 2 groups
{
    // issue all 8 loads first (MLP=8), then convert+store
    const float4 v0 = src[0], v1 = src[1], v2 = src[2], v3 = src[3];
    const float4 v4 = src[4], v5 = src[5], v6 = src[6], v7 = src[7];
    uint4 o0, o1, o2, o3;
    o0.x = f2h2(v0.x, v0.y);  o0.y = f2h2(v2.x, v2.y);
    o0.z = f2h2(v0.z, v0.w);  o0.w = f2h2(v2.z, v2.w);
    o1.x = f2h2(v1.x, v1.y);  o1.y = f2h2(v3.x, v3.y);
    o1.z = f2h2(v1.z, v1.w);  o1.w = f2h2(v3.z, v3.w);
    o2.x = f2h2(v4.x, v4.y);  o2.y = f2h2(v6.x, v6.y);
    o2.z = f2h2(v4.z, v4.w);  o2.w = f2h2(v6.z, v6.w);
    o3.x = f2h2(v5.x, v5.y);  o3.y = f2h2(v7.x, v7.y);
    o3.z = f2h2(v5.z, v5.w);  o3.w = f2h2(v7.z, v7.w);
    dst[0] = o0;
    dst[1] = o1;
    dst[2] = o2;
    dst[3] = o3;
}

__global__ void prepass_kernel(const float4* __restrict__ x,
                               const float4* __restrict__ wq,
                               const float4* __restrict__ wk,
                               const float4* __restrict__ wv,
                               const float4* __restrict__ wo)
{
    const int p = blockIdx.x * blockDim.x + threadIdx.x;   // pair index
    if (p >= NPREP2) return;
    const int i = 2 * p;                                   // first group idx
    uint4* X4 = reinterpret_cast<uint4*>(g_X);
    uint4* W4 = reinterpret_cast<uint4*>(g_Wall);
    if (i < NXG) {
        perm32(&x[4 * i], &X4[2 * i]);
    } else {
        const int j = i - NXG;
        const int w = j >> 16;          // which weight matrix (NWG = 1<<16)
        const int gidx = j & (NWG - 1); // even, so gidx+1 stays in-matrix
        const float4* src = (w == 0) ? wq : (w == 1) ? wk : (w == 2) ? wv : wo;
        perm32(&src[4 * gidx], &W4[2 * (gidx + w * NWG)]);
    }
}

// ---------------------------------------------------------------------------
// fp16 GEMM (champion config — byte-identical): 128x128 CTA tile, BK=32,
// 4-stage cp.async, 8 warps 4(M)x2(N), warp tile 32x64, m16n8k16.
// MODE 0: fp32 [M,N].  MODE 1: half scatter [B,H,T,dk] dk-perm (scaled).
// MODE 2: half scatter TRANSPOSED [B,H,dk,T].
// ---------------------------------------------------------------------------
#define GTS 48
#define G_TILE (128 * GTS)                    // halves per tile per stage
#define GEMM_SMEM_BYTES (4 * 2 * G_TILE * 2)  // 98304
#define NKB32 (DM / 32)                       // 32

template <int MODE>
__device__ __forceinline__ void gemm_body(const __half* __restrict__ X,
                                          const __half* __restrict__ W,
                                          const float* __restrict__ bias,
                                          void* __restrict__ Yv,
                                          float scl)
{
    extern __shared__ __half smh[];

    const int tid  = threadIdx.x;
    const int warp = tid >> 5, lane = tid & 31;
    const int g = lane >> 2, t = lane & 3;
    const int wm = warp >> 1;
    const int wn = warp & 1;
    const int m0 = blockIdx.y * 128;
    const int n0 = blockIdx.x * 128;

    const int lr = tid >> 2;            // 0..63
    const int lc = (tid & 3) * 8;       // 0,8,16,24 halves

    auto stage_load = [&](int kb) {
        __half* Xs = smh + (kb & 3) * (2 * G_TILE);
        __half* Ws = Xs + G_TILE;
        const int k0 = kb * 32;
        cp16h(&Xs[lr * GTS + lc],        &X[(size_t)(m0 + lr     ) * DM + k0 + lc]);
        cp16h(&Xs[(lr + 64) * GTS + lc], &X[(size_t)(m0 + lr + 64) * DM + k0 + lc]);
        cp16h(&Ws[lr * GTS + lc],        &W[(size_t)(n0 + lr     ) * DM + k0 + lc]);
        cp16h(&Ws[(lr + 64) * GTS + lc], &W[(size_t)(n0 + lr + 64) * DM + k0 + lc]);
    };

    stage_load(0); cp_commit();
    stage_load(1); cp_commit();
    stage_load(2); cp_commit();

    float acc[2][8][4] = {};

    const int aoff = (wm * 32 + g) * GTS + 4 * t;
    const int boff = (wn * 64 + g) * GTS + 4 * t;

#pragma unroll 4
    for (int kb = 0; kb < NKB32; kb++) {
        cp_wait<2>();
        __syncthreads();

        if (kb + 3 < NKB32) stage_load(kb + 3);
        cp_commit();

        const __half* Xc = smh + (kb & 3) * (2 * G_TILE);
        const __half* Wc = Xc + G_TILE;
#pragma unroll
        for (int kk = 0; kk < 2; kk++) {
            const int ko = kk * 16;
            uint2 aL[2], aH[2];
#pragma unroll
            for (int mf = 0; mf < 2; mf++) {
                aL[mf] = *reinterpret_cast<const uint2*>(Xc + aoff + mf * 16 * GTS + ko);
                aH[mf] = *reinterpret_cast<const uint2*>(Xc + aoff + mf * 16 * GTS + 8 * GTS + ko);
            }
#pragma unroll
            for (int nf = 0; nf < 8; nf++) {
                const uint2 bb =
                    *reinterpret_cast<const uint2*>(Wc + boff + nf * 8 * GTS + ko);
#pragma unroll
                for (int mf = 0; mf < 2; mf++)
                    mma_f16(acc[mf][nf], aL[mf].x, aH[mf].x, aL[mf].y, aH[mf].y,
                            bb.x, bb.y);
            }
        }
    }

    // Epilogue
#pragma unroll
    for (int mf = 0; mf < 2; mf++) {
        const int m = m0 + wm * 32 + mf * 16 + g;
#pragma unroll
        for (int nf = 0; nf < 8; nf++) {
            const int n = n0 + wn * 64 + nf * 8 + 2 * t;
            const float v0 = acc[mf][nf][0] + bias[n];
            const float v1 = acc[mf][nf][1] + bias[n + 1];
            const float v2 = acc[mf][nf][2] + bias[n];
            const float v3 = acc[mf][nf][3] + bias[n + 1];
            if (MODE == 0) {
                float* Y = (float*)Yv;
                *reinterpret_cast<float2*>(&Y[(size_t)m * DM + n]) = make_float2(v0, v1);
                *reinterpret_cast<float2*>(&Y[(size_t)(m + 8) * DM + n]) = make_float2(v2, v3);
            } else if (MODE == 1) {
                __half* Y = (__half*)Yv;
                const int nb_ = n0 + wn * 64 + nf * 8;
                const int h_  = nb_ >> 6;
                const int pos = ((nf >> 1) << 4) + 4 * t + ((nf & 1) << 1);
                const int b0_ = m / SEQ, t0_ = m % SEQ;
                const int b1_ = (m + 8) / SEQ, t1_ = (m + 8) % SEQ;
                __half* y0 = &Y[(((size_t)b0_ * HEADS + h_) * SEQ + t0_) * DK];
                __half* y1 = &Y[(((size_t)b1_ * HEADS + h_) * SEQ + t1_) * DK];
                *reinterpret_cast<uint32_t*>(&y0[pos]) = f2h2(v0 * scl, v1 * scl);
                *reinterpret_cast<uint32_t*>(&y1[pos]) = f2h2(v2 * scl, v3 * scl);
            } else {
                __half* Y = (__half*)Yv;
                const int h_ = n >> 6;
                const int d0 = n & 63, d1 = d0 + 1;
                const int b0_ = m / SEQ, t0_ = m % SEQ;
                const int b1_ = (m + 8) / SEQ, t1_ = (m + 8) % SEQ;
                const size_t hb0 = ((size_t)b0_ * HEADS + h_) * DK;
                const size_t hb1 = ((size_t)b1_ * HEADS + h_) * DK;
                Y[(hb0 + d0) * SEQ + t0_] = __float2half_rn(v0);
                Y[(hb0 + d1) * SEQ + t0_] = __float2half_rn(v1);
                Y[(hb1 + d0) * SEQ + t1_] = __float2half_rn(v2);
                Y[(hb1 + d1) * SEQ + t1_] = __float2half_rn(v3);
            }
        }
    }
}

__global__ __launch_bounds__(256, 2)
void gemm_qkv_kernel(const float* __restrict__ bq,
                     const float* __restrict__ bk,
                     const float* __restrict__ bv)
{
    const int z = blockIdx.z;
    const __half* W = g_Wall + (size_t)z * DM * DM;
    const float qscale = 0.125f * 1.4426950408889634f;
    if (z == 0)      gemm_body<1>(g_X, W, bq, g_Q, qscale);
    else if (z == 1) gemm_body<1>(g_X, W, bk, g_K, 1.f);
    else             gemm_body<2>(g_X, W, bv, g_V, 1.f);
}

__global__ __launch_bounds__(256, 2)
void gemm_out_kernel(const float* __restrict__ bo, float* __restrict__ Y)
{
    gemm_body<0>(g_ctx, g_Wall + (size_t)3 * DM * DM, bo, Y, 1.f);
}

// ---------------------------------------------------------------------------
// Flash attention (champion config — byte-identical): fp16 mma, 4-stage KV
// pipeline (BKV=64). Q/K dk-permuted (Q pre-scaled); V [dk][T].
// ---------------------------------------------------------------------------
#define QST 80
#define KST 80
#define VST 72
#define BKV 64
#define Q_HALFS (128 * QST)
#define A_STAGE (BKV * KST + DK * VST)                     // 9728
#define ATTN_SMEM_BYTES ((Q_HALFS + 4 * A_STAGE) * 2)      // 98304

__global__ __launch_bounds__(256, 2)
void attn_f16_kernel()
{
    extern __shared__ __half smh[];
    __half* Qs = smh;

    const int tid  = threadIdx.x;
    const int warp = tid >> 5, lane = tid & 31;
    const int g = lane >> 2, t = lane & 3;
    const int qb = blockIdx.x;
    const int h  = blockIdx.y;
    const int b  = blockIdx.z;

    const size_t head_qk = ((size_t)b * HEADS + h) * SEQ * DK;
    const __half* Qg = g_Q + head_qk + (size_t)qb * 128 * DK;
    const __half* Kg = g_K + head_qk;
    const __half* Vg = g_V + ((size_t)b * HEADS + h) * DK * SEQ;

    const int lr = tid >> 3;
    const int lc = (tid & 7) * 8;

    auto stage_load = [&](int it) {
        __half* Ks = smh + Q_HALFS + (it & 3) * A_STAGE;
        __half* Vs = Ks + BKV * KST;
        const int kb = it * BKV;
        cp16h(&Ks[lr * KST + lc],        &Kg[(size_t)(kb + lr     ) * DK + lc]);
        cp16h(&Ks[(lr + 32) * KST + lc], &Kg[(size_t)(kb + lr + 32) * DK + lc]);
        cp16h(&Vs[lr * VST + lc],        &Vg[(size_t)(lr     ) * SEQ + kb + lc]);
        cp16h(&Vs[(lr + 32) * VST + lc], &Vg[(size_t)(lr + 32) * SEQ + kb + lc]);
    };

#pragma unroll
    for (int i = 0; i < 4; i++) {
        const int row = lr + i * 32;
        cp16h(&Qs[row * QST + lc], &Qg[(size_t)row * DK + lc]);
    }
    stage_load(0); cp_commit();
    stage_load(1); cp_commit();
    stage_load(2); cp_commit();

    float O[8][4] = {};
    float mrow0 = -INFINITY, mrow1 = -INFINITY;
    float lrow0 = 0.f, lrow1 = 0.f;

    const int qrow = warp * 16;
    const int qoff = (qrow + g) * QST + 4 * t;
    const int koff = g * KST + 4 * t;
    const int NT = SEQ / BKV;   // 32

    for (int it = 0; it < NT; it++) {
        cp_wait<2>();
        __syncthreads();

        if (it + 3 < NT) stage_load(it + 3);
        cp_commit();

        const __half* Kc = smh + Q_HALFS + (it & 3) * A_STAGE;
        const __half* Vc = Kc + BKV * KST;

        float s[8][4] = {};
#pragma unroll
        for (int kk = 0; kk < 4; kk++) {
            const int ko = kk * 16;
            const uint2 aL = *reinterpret_cast<const uint2*>(Qs + qoff + ko);
            const uint2 aH = *reinterpret_cast<const uint2*>(Qs + qoff + 8 * QST + ko);
#pragma unroll
            for (int nf = 0; nf < 8; nf++) {
                const uint2 bb =
                    *reinterpret_cast<const uint2*>(Kc + koff + nf * 8 * KST + ko);
                mma_f16(s[nf], aL.x, aH.x, aL.y, aH.y, bb.x, bb.y);
            }
        }

        float ml0 = -INFINITY, ml1 = -INFINITY;
#pragma unroll
        for (int nf = 0; nf < 8; nf++) {
            ml0 = fmaxf(ml0, fmaxf(s[nf][0], s[nf][1]));
            ml1 = fmaxf(ml1, fmaxf(s[nf][2], s[nf][3]));
        }
        ml0 = fmaxf(ml0, __shfl_xor_sync(0xffffffffu, ml0, 1));
        ml0 = fmaxf(ml0, __shfl_xor_sync(0xffffffffu, ml0, 2));
        ml1 = fmaxf(ml1, __shfl_xor_sync(0xffffffffu, ml1, 1));
        ml1 = fmaxf(ml1, __shfl_xor_sync(0xffffffffu, ml1, 2));
        const float mn0 = fmaxf(mrow0, ml0);
        const float mn1 = fmaxf(mrow1, ml1);
        const float alpha0 = ex2f_(mrow0 - mn0);
        const float alpha1 = ex2f_(mrow1 - mn1);

        float rs0 = 0.f, rs1 = 0.f;
        uint32_t ph[16];   // P as half2 A-frag words: [nf][lo(g)/hi(g+8)]
#pragma unroll
        for (int nf = 0; nf < 8; nf++) {
            const float p0 = ex2f_(s[nf][0] - mn0);
            const float p1 = ex2f_(s[nf][1] - mn0);
            const float p2 = ex2f_(s[nf][2] - mn1);
            const float p3 = ex2f_(s[nf][3] - mn1);
            rs0 += p0 + p1;
            rs1 += p2 + p3;
            ph[2 * nf]     = f2h2(p0, p1);
            ph[2 * nf + 1] = f2h2(p2, p3);
        }
        rs0 += __shfl_xor_sync(0xffffffffu, rs0, 1);
        rs0 += __shfl_xor_sync(0xffffffffu, rs0, 2);
        rs1 += __shfl_xor_sync(0xffffffffu, rs1, 1);
        rs1 += __shfl_xor_sync(0xffffffffu, rs1, 2);

        if (__any_sync(0xffffffffu, (alpha0 < 1.f) | (alpha1 < 1.f))) {
#pragma unroll
            for (int nf = 0; nf < 8; nf++) {
                O[nf][0] *= alpha0; O[nf][1] *= alpha0;
                O[nf][2] *= alpha1; O[nf][3] *= alpha1;
            }
        }
        lrow0 = lrow0 * alpha0 + rs0;
        lrow1 = lrow1 * alpha1 + rs1;
        mrow0 = mn0; mrow1 = mn1;

        // O += P @ V : A frags direct from ph; B from transposed V tile
#pragma unroll
        for (int kk = 0; kk < 4; kk++) {
            const uint32_t a0 = ph[4 * kk];
            const uint32_t a1 = ph[4 * kk + 1];
            const uint32_t a2 = ph[4 * kk + 2];
            const uint32_t a3 = ph[4 * kk + 3];
            const int kvo = kk * 16 + 2 * t;
#pragma unroll
            for (int nf = 0; nf < 8; nf++) {
                const __half* vr = Vc + (nf * 8 + g) * VST + kvo;
                const uint32_t b0 = *reinterpret_cast<const uint32_t*>(vr);
                const uint32_t b1 = *reinterpret_cast<const uint32_t*>(vr + 8);
                mma_f16(O[nf], a0, a1, a2, a3, b0, b1);
            }
        }
    }

    // Epilogue: normalize, write ctx half, feature-permuted (matches Wo).
    const float inv0 = 1.f / lrow0;
    const float inv1 = 1.f / lrow1;
    const int t0 = qb * 128 + qrow + g;
#pragma unroll
    for (int nf = 0; nf < 8; nf++) {
        const int g16 = h * DK + ((nf >> 1) << 4);
        const int pos = g16 + 4 * t + ((nf & 1) << 1);
        __half* r0 = &g_ctx[((size_t)b * SEQ + t0    ) * DM];
        __half* r1 = &g_ctx[((size_t)b * SEQ + t0 + 8) * DM];
        *reinterpret_cast<uint32_t*>(&r0[pos]) = f2h2(O[nf][0] * inv0, O[nf][1] * inv0);
        *reinterpret_cast<uint32_t*>(&r1[pos]) = f2h2(O[nf][2] * inv1, O[nf][3] * inv1);
    }
}

// ---------------------------------------------------------------------------
// Launch. Inputs: x, W_q, b_q, W_k, b_k, W_v, b_v, W_out, b_out
// ---------------------------------------------------------------------------
extern "C" void kernel_launch(void* const* d_in, const int* in_sizes, int n_in,
                              void* d_out, int out_size)
{
    const float* b_q = (const float*)d_in[2];
    const float* b_k = (const float*)d_in[4];
    const float* b_v = (const float*)d_in[6];
    const float* b_o = (const float*)d_in[8];

    cudaFuncSetAttribute(gemm_qkv_kernel,
                         cudaFuncAttributeMaxDynamicSharedMemorySize, GEMM_SMEM_BYTES);
    cudaFuncSetAttribute(gemm_out_kernel,
                         cudaFuncAttributeMaxDynamicSharedMemorySize, GEMM_SMEM_BYTES);
    cudaFuncSetAttribute(attn_f16_kernel,
                         cudaFuncAttributeMaxDynamicSharedMemorySize, ATTN_SMEM_BYTES);

    prepass_kernel<<<(NPREP2 + 255) / 256, 256>>>(
        (const float4*)d_in[0], (const float4*)d_in[1], (const float4*)d_in[3],
        (const float4*)d_in[5], (const float4*)d_in[7]);

    gemm_qkv_kernel<<<dim3(DM / 128, MROWS / 128, 3), 256, GEMM_SMEM_BYTES>>>(
        b_q, b_k, b_v);

    attn_f16_kernel<<<dim3(SEQ / 128, HEADS, BATCH), 256, ATTN_SMEM_BYTES>>>();

    gemm_out_kernel<<<dim3(DM / 128, MROWS / 128), 256, GEMM_SMEM_BYTES>>>(
        b_o, (float*)d_out);
}

// round 17
// speedup vs baseline: 1.0171x; 1.0171x over previous
#include <cuda_runtime.h>
#include <cuda_fp16.h>
#include <math.h>
#include <stdint.h>

// Problem constants
#define BATCH 2
#define SEQ   2048
#define HEADS 16
#define DK    64
#define DM    1024
#define MROWS (BATCH * SEQ)   // 4096

// Scratch (device globals — no allocation allowed).
// All half tensors keep the contraction dim PERMUTED within 16-groups:
// stored order [0,1,8,9, 2,3,10,11, 4,5,12,13, 6,7,14,15], so an fp16 mma
// fragment's k-pair regs {(2t,2t+1),(2t+8,2t+9)} are 4 contiguous halves.
__device__ __half g_X[MROWS * DM];                  // k permuted
__device__ __half g_Wall[4 * DM * DM];              // k permuted
__device__ __half g_Q[BATCH * HEADS * SEQ * DK];    // dk permuted, pre-scaled
__device__ __half g_K[BATCH * HEADS * SEQ * DK];    // dk permuted
__device__ __half g_V[BATCH * HEADS * DK * SEQ];    // TRANSPOSED [B,H,dk,T]
__device__ __half g_ctx[MROWS * DM];                // feature permuted

__device__ __forceinline__ uint32_t f2h2(float a, float b) {
    __half2 h = __floats2half2_rn(a, b);
    return *reinterpret_cast<uint32_t*>(&h);
}
__device__ __forceinline__ float ex2f_(float x) {
    float y;
    asm("ex2.approx.ftz.f32 %0, %1;" : "=f"(y) : "f"(x));
    return y;
}

__device__ __forceinline__ void mma_f16(float c[4],
    uint32_t a0, uint32_t a1, uint32_t a2, uint32_t a3,
    uint32_t b0, uint32_t b1)
{
    asm volatile(
        "mma.sync.aligned.m16n8k16.row.col.f32.f16.f16.f32 "
        "{%0,%1,%2,%3}, {%4,%5,%6,%7}, {%8,%9}, {%0,%1,%2,%3};\n"
        : "+f"(c[0]), "+f"(c[1]), "+f"(c[2]), "+f"(c[3])
        : "r"(a0), "r"(a1), "r"(a2), "r"(a3), "r"(b0), "r"(b1));
}

__device__ __forceinline__ void cp16h(__half* smem_dst, const __half* gsrc) {
    uint32_t s = (uint32_t)__cvta_generic_to_shared(smem_dst);
    asm volatile("cp.async.cg.shared.global [%0], [%1], 16;\n" :: "r"(s), "l"(gsrc));
}
__device__ __forceinline__ void cp_commit() {
    asm volatile("cp.async.commit_group;\n");
}
template <int N>
__device__ __forceinline__ void cp_wait() {
    asm volatile("cp.async.wait_group %0;\n" :: "n"(N));
}

// ---------------------------------------------------------------------------
// Prepass (R15 champion form): fp32 -> fp16 with 16-group k-permutation,
// load-balanced (one 16-float group per thread, flat index space),
// vectorized: 4x LDG.128 in, 2x STG.128 out.
// ---------------------------------------------------------------------------
#define NXG (MROWS * DM / 16)   // 262144 x-groups
#define NWG (DM * DM / 16)      // 65536 groups per weight matrix
#define NPREP (NXG + 4 * NWG)   // 524288 total

__device__ __forceinline__ void perm16(const float4* __restrict__ src,
                                       uint4* __restrict__ dst)   // 2x uint4
{
    const float4 v0 = src[0], v1 = src[1], v2 = src[2], v3 = src[3];
    uint4 o0, o1;
    o0.x = f2h2(v0.x, v0.y);  o0.y = f2h2(v2.x, v2.y);
    o0.z = f2h2(v0.z, v0.w);  o0.w = f2h2(v2.z, v2.w);
    o1.x = f2h2(v1.x, v1.y);  o1.y = f2h2(v3.x, v3.y);
    o1.z = f2h2(v1.z, v1.w);  o1.w = f2h2(v3.z, v3.w);
    dst[0] = o0;
    dst[1] = o1;
}

__global__ void prepass_kernel(const float4* __restrict__ x,
                               const float4* __restrict__ wq,
                               const float4* __restrict__ wk,
                               const float4* __restrict__ wv,
                               const float4* __restrict__ wo)
{
    const int i = blockIdx.x * blockDim.x + threadIdx.x;
    if (i >= NPREP) return;
    uint4* X4 = reinterpret_cast<uint4*>(g_X);
    uint4* W4 = reinterpret_cast<uint4*>(g_Wall);
    if (i < NXG) {
        perm16(&x[4 * i], &X4[2 * i]);
    } else {
        const int j = i - NXG;
        const int w = j >> 16;          // which weight matrix (NWG = 1<<16)
        const int gidx = j & (NWG - 1);
        const float4* src = (w == 0) ? wq : (w == 1) ? wk : (w == 2) ? wv : wo;
        perm16(&src[4 * gidx], &W4[2 * (gidx + w * NWG)]);
    }
}

// ---------------------------------------------------------------------------
// fp16 GEMM (champion config — byte-identical): 128x128 CTA tile, BK=32,
// 4-stage cp.async, 8 warps 4(M)x2(N), warp tile 32x64, m16n8k16.
// MODE 0: fp32 [M,N].  MODE 1: half scatter [B,H,T,dk] dk-perm (scaled).
// MODE 2: half scatter TRANSPOSED [B,H,dk,T].
// ---------------------------------------------------------------------------
#define GTS 48
#define G_TILE (128 * GTS)                    // halves per tile per stage
#define GEMM_SMEM_BYTES (4 * 2 * G_TILE * 2)  // 98304
#define NKB32 (DM / 32)                       // 32

template <int MODE>
__device__ __forceinline__ void gemm_body(const __half* __restrict__ X,
                                          const __half* __restrict__ W,
                                          const float* __restrict__ bias,
                                          void* __restrict__ Yv,
                                          float scl)
{
    extern __shared__ __half smh[];

    const int tid  = threadIdx.x;
    const int warp = tid >> 5, lane = tid & 31;
    const int g = lane >> 2, t = lane & 3;
    const int wm = warp >> 1;
    const int wn = warp & 1;
    const int m0 = blockIdx.y * 128;
    const int n0 = blockIdx.x * 128;

    const int lr = tid >> 2;            // 0..63
    const int lc = (tid & 3) * 8;       // 0,8,16,24 halves

    auto stage_load = [&](int kb) {
        __half* Xs = smh + (kb & 3) * (2 * G_TILE);
        __half* Ws = Xs + G_TILE;
        const int k0 = kb * 32;
        cp16h(&Xs[lr * GTS + lc],        &X[(size_t)(m0 + lr     ) * DM + k0 + lc]);
        cp16h(&Xs[(lr + 64) * GTS + lc], &X[(size_t)(m0 + lr + 64) * DM + k0 + lc]);
        cp16h(&Ws[lr * GTS + lc],        &W[(size_t)(n0 + lr     ) * DM + k0 + lc]);
        cp16h(&Ws[(lr + 64) * GTS + lc], &W[(size_t)(n0 + lr + 64) * DM + k0 + lc]);
    };

    stage_load(0); cp_commit();
    stage_load(1); cp_commit();
    stage_load(2); cp_commit();

    float acc[2][8][4] = {};

    const int aoff = (wm * 32 + g) * GTS + 4 * t;
    const int boff = (wn * 64 + g) * GTS + 4 * t;

#pragma unroll 4
    for (int kb = 0; kb < NKB32; kb++) {
        cp_wait<2>();
        __syncthreads();

        if (kb + 3 < NKB32) stage_load(kb + 3);
        cp_commit();

        const __half* Xc = smh + (kb & 3) * (2 * G_TILE);
        const __half* Wc = Xc + G_TILE;
#pragma unroll
        for (int kk = 0; kk < 2; kk++) {
            const int ko = kk * 16;
            uint2 aL[2], aH[2];
#pragma unroll
            for (int mf = 0; mf < 2; mf++) {
                aL[mf] = *reinterpret_cast<const uint2*>(Xc + aoff + mf * 16 * GTS + ko);
                aH[mf] = *reinterpret_cast<const uint2*>(Xc + aoff + mf * 16 * GTS + 8 * GTS + ko);
            }
#pragma unroll
            for (int nf = 0; nf < 8; nf++) {
                const uint2 bb =
                    *reinterpret_cast<const uint2*>(Wc + boff + nf * 8 * GTS + ko);
#pragma unroll
                for (int mf = 0; mf < 2; mf++)
                    mma_f16(acc[mf][nf], aL[mf].x, aH[mf].x, aL[mf].y, aH[mf].y,
                            bb.x, bb.y);
            }
        }
    }

    // Epilogue
#pragma unroll
    for (int mf = 0; mf < 2; mf++) {
        const int m = m0 + wm * 32 + mf * 16 + g;
#pragma unroll
        for (int nf = 0; nf < 8; nf++) {
            const int n = n0 + wn * 64 + nf * 8 + 2 * t;
            const float v0 = acc[mf][nf][0] + bias[n];
            const float v1 = acc[mf][nf][1] + bias[n + 1];
            const float v2 = acc[mf][nf][2] + bias[n];
            const float v3 = acc[mf][nf][3] + bias[n + 1];
            if (MODE == 0) {
                float* Y = (float*)Yv;
                *reinterpret_cast<float2*>(&Y[(size_t)m * DM + n]) = make_float2(v0, v1);
                *reinterpret_cast<float2*>(&Y[(size_t)(m + 8) * DM + n]) = make_float2(v2, v3);
            } else if (MODE == 1) {
                __half* Y = (__half*)Yv;
                const int nb_ = n0 + wn * 64 + nf * 8;
                const int h_  = nb_ >> 6;
                const int pos = ((nf >> 1) << 4) + 4 * t + ((nf & 1) << 1);
                const int b0_ = m / SEQ, t0_ = m % SEQ;
                const int b1_ = (m + 8) / SEQ, t1_ = (m + 8) % SEQ;
                __half* y0 = &Y[(((size_t)b0_ * HEADS + h_) * SEQ + t0_) * DK];
                __half* y1 = &Y[(((size_t)b1_ * HEADS + h_) * SEQ + t1_) * DK];
                *reinterpret_cast<uint32_t*>(&y0[pos]) = f2h2(v0 * scl, v1 * scl);
                *reinterpret_cast<uint32_t*>(&y1[pos]) = f2h2(v2 * scl, v3 * scl);
            } else {
                __half* Y = (__half*)Yv;
                const int h_ = n >> 6;
                const int d0 = n & 63, d1 = d0 + 1;
                const int b0_ = m / SEQ, t0_ = m % SEQ;
                const int b1_ = (m + 8) / SEQ, t1_ = (m + 8) % SEQ;
                const size_t hb0 = ((size_t)b0_ * HEADS + h_) * DK;
                const size_t hb1 = ((size_t)b1_ * HEADS + h_) * DK;
                Y[(hb0 + d0) * SEQ + t0_] = __float2half_rn(v0);
                Y[(hb0 + d1) * SEQ + t0_] = __float2half_rn(v1);
                Y[(hb1 + d0) * SEQ + t1_] = __float2half_rn(v2);
                Y[(hb1 + d1) * SEQ + t1_] = __float2half_rn(v3);
            }
        }
    }
}

__global__ __launch_bounds__(256, 2)
void gemm_qkv_kernel(const float* __restrict__ bq,
                     const float* __restrict__ bk,
                     const float* __restrict__ bv)
{
    const int z = blockIdx.z;
    const __half* W = g_Wall + (size_t)z * DM * DM;
    const float qscale = 0.125f * 1.4426950408889634f;
    if (z == 0)      gemm_body<1>(g_X, W, bq, g_Q, qscale);
    else if (z == 1) gemm_body<1>(g_X, W, bk, g_K, 1.f);
    else             gemm_body<2>(g_X, W, bv, g_V, 1.f);
}

__global__ __launch_bounds__(256, 2)
void gemm_out_kernel(const float* __restrict__ bo, float* __restrict__ Y)
{
    gemm_body<0>(g_ctx, g_Wall + (size_t)3 * DM * DM, bo, Y, 1.f);
}

// ---------------------------------------------------------------------------
// Flash attention (champion config — byte-identical): fp16 mma, 4-stage KV
// pipeline (BKV=64). Q/K dk-permuted (Q pre-scaled); V [dk][T].
// ---------------------------------------------------------------------------
#define QST 80
#define KST 80
#define VST 72
#define BKV 64
#define Q_HALFS (128 * QST)
#define A_STAGE (BKV * KST + DK * VST)                     // 9728
#define ATTN_SMEM_BYTES ((Q_HALFS + 4 * A_STAGE) * 2)      // 98304

__global__ __launch_bounds__(256, 2)
void attn_f16_kernel()
{
    extern __shared__ __half smh[];
    __half* Qs = smh;

    const int tid  = threadIdx.x;
    const int warp = tid >> 5, lane = tid & 31;
    const int g = lane >> 2, t = lane & 3;
    const int qb = blockIdx.x;
    const int h  = blockIdx.y;
    const int b  = blockIdx.z;

    const size_t head_qk = ((size_t)b * HEADS + h) * SEQ * DK;
    const __half* Qg = g_Q + head_qk + (size_t)qb * 128 * DK;
    const __half* Kg = g_K + head_qk;
    const __half* Vg = g_V + ((size_t)b * HEADS + h) * DK * SEQ;

    const int lr = tid >> 3;
    const int lc = (tid & 7) * 8;

    auto stage_load = [&](int it) {
        __half* Ks = smh + Q_HALFS + (it & 3) * A_STAGE;
        __half* Vs = Ks + BKV * KST;
        const int kb = it * BKV;
        cp16h(&Ks[lr * KST + lc],        &Kg[(size_t)(kb + lr     ) * DK + lc]);
        cp16h(&Ks[(lr + 32) * KST + lc], &Kg[(size_t)(kb + lr + 32) * DK + lc]);
        cp16h(&Vs[lr * VST + lc],        &Vg[(size_t)(lr     ) * SEQ + kb + lc]);
        cp16h(&Vs[(lr + 32) * VST + lc], &Vg[(size_t)(lr + 32) * SEQ + kb + lc]);
    };

#pragma unroll
    for (int i = 0; i < 4; i++) {
        const int row = lr + i * 32;
        cp16h(&Qs[row * QST + lc], &Qg[(size_t)row * DK + lc]);
    }
    stage_load(0); cp_commit();
    stage_load(1); cp_commit();
    stage_load(2); cp_commit();

    float O[8][4] = {};
    float mrow0 = -INFINITY, mrow1 = -INFINITY;
    float lrow0 = 0.f, lrow1 = 0.f;

    const int qrow = warp * 16;
    const int qoff = (qrow + g) * QST + 4 * t;
    const int koff = g * KST + 4 * t;
    const int NT = SEQ / BKV;   // 32

    for (int it = 0; it < NT; it++) {
        cp_wait<2>();
        __syncthreads();

        if (it + 3 < NT) stage_load(it + 3);
        cp_commit();

        const __half* Kc = smh + Q_HALFS + (it & 3) * A_STAGE;
        const __half* Vc = Kc + BKV * KST;

        float s[8][4] = {};
#pragma unroll
        for (int kk = 0; kk < 4; kk++) {
            const int ko = kk * 16;
            const uint2 aL = *reinterpret_cast<const uint2*>(Qs + qoff + ko);
            const uint2 aH = *reinterpret_cast<const uint2*>(Qs + qoff + 8 * QST + ko);
#pragma unroll
            for (int nf = 0; nf < 8; nf++) {
                const uint2 bb =
                    *reinterpret_cast<const uint2*>(Kc + koff + nf * 8 * KST + ko);
                mma_f16(s[nf], aL.x, aH.x, aL.y, aH.y, bb.x, bb.y);
            }
        }

        float ml0 = -INFINITY, ml1 = -INFINITY;
#pragma unroll
        for (int nf = 0; nf < 8; nf++) {
            ml0 = fmaxf(ml0, fmaxf(s[nf][0], s[nf][1]));
            ml1 = fmaxf(ml1, fmaxf(s[nf][2], s[nf][3]));
        }
        ml0 = fmaxf(ml0, __shfl_xor_sync(0xffffffffu, ml0, 1));
        ml0 = fmaxf(ml0, __shfl_xor_sync(0xffffffffu, ml0, 2));
        ml1 = fmaxf(ml1, __shfl_xor_sync(0xffffffffu, ml1, 1));
        ml1 = fmaxf(ml1, __shfl_xor_sync(0xffffffffu, ml1, 2));
        const float mn0 = fmaxf(mrow0, ml0);
        const float mn1 = fmaxf(mrow1, ml1);
        const float alpha0 = ex2f_(mrow0 - mn0);
        const float alpha1 = ex2f_(mrow1 - mn1);

        float rs0 = 0.f, rs1 = 0.f;
        uint32_t ph[16];   // P as half2 A-frag words: [nf][lo(g)/hi(g+8)]
#pragma unroll
        for (int nf = 0; nf < 8; nf++) {
            const float p0 = ex2f_(s[nf][0] - mn0);
            const float p1 = ex2f_(s[nf][1] - mn0);
            const float p2 = ex2f_(s[nf][2] - mn1);
            const float p3 = ex2f_(s[nf][3] - mn1);
            rs0 += p0 + p1;
            rs1 += p2 + p3;
            ph[2 * nf]     = f2h2(p0, p1);
            ph[2 * nf + 1] = f2h2(p2, p3);
        }
        rs0 += __shfl_xor_sync(0xffffffffu, rs0, 1);
        rs0 += __shfl_xor_sync(0xffffffffu, rs0, 2);
        rs1 += __shfl_xor_sync(0xffffffffu, rs1, 1);
        rs1 += __shfl_xor_sync(0xffffffffu, rs1, 2);

        if (__any_sync(0xffffffffu, (alpha0 < 1.f) | (alpha1 < 1.f))) {
#pragma unroll
            for (int nf = 0; nf < 8; nf++) {
                O[nf][0] *= alpha0; O[nf][1] *= alpha0;
                O[nf][2] *= alpha1; O[nf][3] *= alpha1;
            }
        }
        lrow0 = lrow0 * alpha0 + rs0;
        lrow1 = lrow1 * alpha1 + rs1;
        mrow0 = mn0; mrow1 = mn1;

        // O += P @ V : A frags direct from ph; B from transposed V tile
#pragma unroll
        for (int kk = 0; kk < 4; kk++) {
            const uint32_t a0 = ph[4 * kk];
            const uint32_t a1 = ph[4 * kk + 1];
            const uint32_t a2 = ph[4 * kk + 2];
            const uint32_t a3 = ph[4 * kk + 3];
            const int kvo = kk * 16 + 2 * t;
#pragma unroll
            for (int nf = 0; nf < 8; nf++) {
                const __half* vr = Vc + (nf * 8 + g) * VST + kvo;
                const uint32_t b0 = *reinterpret_cast<const uint32_t*>(vr);
                const uint32_t b1 = *reinterpret_cast<const uint32_t*>(vr + 8);
                mma_f16(O[nf], a0, a1, a2, a3, b0, b1);
            }
        }
    }

    // Epilogue: normalize, write ctx half, feature-permuted (matches Wo).
    const float inv0 = 1.f / lrow0;
    const float inv1 = 1.f / lrow1;
    const int t0 = qb * 128 + qrow + g;
#pragma unroll
    for (int nf = 0; nf < 8; nf++) {
        const int g16 = h * DK + ((nf >> 1) << 4);
        const int pos = g16 + 4 * t + ((nf & 1) << 1);
        __half* r0 = &g_ctx[((size_t)b * SEQ + t0    ) * DM];
        __half* r1 = &g_ctx[((size_t)b * SEQ + t0 + 8) * DM];
        *reinterpret_cast<uint32_t*>(&r0[pos]) = f2h2(O[nf][0] * inv0, O[nf][1] * inv0);
        *reinterpret_cast<uint32_t*>(&r1[pos]) = f2h2(O[nf][2] * inv1, O[nf][3] * inv1);
    }
}

// ---------------------------------------------------------------------------
// Launch. Inputs: x, W_q, b_q, W_k, b_k, W_v, b_v, W_out, b_out
// ---------------------------------------------------------------------------
extern "C" void kernel_launch(void* const* d_in, const int* in_sizes, int n_in,
                              void* d_out, int out_size)
{
    const float* b_q = (const float*)d_in[2];
    const float* b_k = (const float*)d_in[4];
    const float* b_v = (const float*)d_in[6];
    const float* b_o = (const float*)d_in[8];

    cudaFuncSetAttribute(gemm_qkv_kernel,
                         cudaFuncAttributeMaxDynamicSharedMemorySize, GEMM_SMEM_BYTES);
    cudaFuncSetAttribute(gemm_out_kernel,
                         cudaFuncAttributeMaxDynamicSharedMemorySize, GEMM_SMEM_BYTES);
    cudaFuncSetAttribute(attn_f16_kernel,
                         cudaFuncAttributeMaxDynamicSharedMemorySize, ATTN_SMEM_BYTES);

    prepass_kernel<<<(NPREP + 255) / 256, 256>>>(
        (const float4*)d_in[0], (const float4*)d_in[1], (const float4*)d_in[3],
        (const float4*)d_in[5], (const float4*)d_in[7]);

    gemm_qkv_kernel<<<dim3(DM / 128, MROWS / 128, 3), 256, GEMM_SMEM_BYTES>>>(
        b_q, b_k, b_v);

    attn_f16_kernel<<<dim3(SEQ / 128, HEADS, BATCH), 256, ATTN_SMEM_BYTES>>>();

    gemm_out_kernel<<<dim3(DM / 128, MROWS / 128), 256, GEMM_SMEM_BYTES>>>(
        b_o, (float*)d_out);
}